// round 16
// baseline (speedup 1.0000x reference)
#include <cuda_runtime.h>
#include <cuda_bf16.h>
#include <cstdint>
#include <cstddef>

// Problem dims (fixed by the dataset): x [4,8192,1024], w [1024,1024], b [1024]
#define D_DIM 1024
#define O_DIM 1024
#define M_MAX 32768
#define NCHUNK 16               // K chunks of 64 bf16 (128B rows)

// ---------------- device scratch (no allocations allowed) ----------------
__device__ int8_t        g_xq[(size_t)M_MAX * D_DIM];   // int8 activations (fallback)
__device__ __nv_bfloat16 g_xb[(size_t)M_MAX * D_DIM];   // bf16 acts, chunk-major + SW128-swizzled
__device__ float         g_rdeq[M_MAX];                 // per-token dequant multiplier
__device__ int8_t        g_wq[(size_t)O_DIM * D_DIM];   // ternary weights int8 (fallback)
__device__ __nv_bfloat16 g_wb[(size_t)O_DIM * D_DIM];   // bf16 weights, chunk-major + swizzled
__device__ float         g_bq[O_DIM];                   // ternary bias as float
__device__ float         g_stats[4];                    // [0]=w_mean [1]=b_mean [2]=1/(ws*bs)
__device__ double2       g_part[1025];                  // per-row partials; [1024] = bias

// ---------------- stage 1a: per-row partial sums ----------------
__global__ void stats_part_kernel(const float* __restrict__ w, const float* __restrict__ b) {
    int blk = blockIdx.x;
    int t = threadIdx.x;

    float4 v;
    if (blk < 1024) v = ((const float4*)w)[blk * 256 + t];
    else            v = ((const float4*)b)[t];

    double s  = (double)v.x + (double)v.y + (double)v.z + (double)v.w;
    double sa = fabs((double)v.x) + fabs((double)v.y) + fabs((double)v.z) + fabs((double)v.w);

    for (int o = 16; o; o >>= 1) {
        s  += __shfl_xor_sync(0xffffffffu, s,  o);
        sa += __shfl_xor_sync(0xffffffffu, sa, o);
    }
    __shared__ double sh[8][2];
    int warp = t >> 5, lane = t & 31;
    if (lane == 0) { sh[warp][0] = s; sh[warp][1] = sa; }
    __syncthreads();
    if (t == 0) {
        double S = 0, SA = 0;
#pragma unroll
        for (int i = 0; i < 8; i++) { S += sh[i][0]; SA += sh[i][1]; }
        g_part[blk] = make_double2(S, SA);
    }
}

// ---------------- stage 1b: final reduction ----------------
__global__ void stats_final_kernel() {
    int t = threadIdx.x;
    double2 p = g_part[t];
    double s = p.x, sa = p.y;

    for (int o = 16; o; o >>= 1) {
        s  += __shfl_xor_sync(0xffffffffu, s,  o);
        sa += __shfl_xor_sync(0xffffffffu, sa, o);
    }
    __shared__ double sh[32][2];
    int warp = t >> 5, lane = t & 31;
    if (lane == 0) { sh[warp][0] = s; sh[warp][1] = sa; }
    __syncthreads();
    if (t == 0) {
        double S = 0, SA = 0;
#pragma unroll
        for (int i = 0; i < 32; i++) { S += sh[i][0]; SA += sh[i][1]; }
        double2 bp = g_part[1024];
        double w_mean  = S  / (double)(O_DIM * D_DIM);
        double w_scale = SA / (double)(O_DIM * D_DIM);
        double b_mean  = bp.x / (double)O_DIM;
        double b_scale = bp.y / (double)O_DIM;
        g_stats[0] = (float)w_mean;
        g_stats[1] = (float)b_mean;
        g_stats[2] = (float)(1.0 / (w_scale * b_scale));
    }
}

// ---------------- stage 2+3 (tc path, fused): quant x AND w/b in one launch ----------------
__global__ void quant_fused_tc_kernel(const float* __restrict__ x,
                                      const float* __restrict__ w,
                                      const float* __restrict__ b, int M) {
    int xblocks = M >> 3;
    if ((int)blockIdx.x < xblocks) {
        int warp = threadIdx.x >> 5, lane = threadIdx.x & 31;
        int m = blockIdx.x * 8 + warp;

        const float4* xr = (const float4*)(x + (size_t)m * D_DIM);
        float4 v[8];
        float ss = 0.f, am = 0.f;
#pragma unroll
        for (int i = 0; i < 8; i++) {
            v[i] = xr[lane + i * 32];
            ss += v[i].x * v[i].x + v[i].y * v[i].y + v[i].z * v[i].z + v[i].w * v[i].w;
            am = fmaxf(am, fmaxf(fmaxf(fabsf(v[i].x), fabsf(v[i].y)),
                                 fmaxf(fabsf(v[i].z), fabsf(v[i].w))));
        }
#pragma unroll
        for (int o = 16; o; o >>= 1) {
            ss += __shfl_xor_sync(0xffffffffu, ss, o);
            am = fmaxf(am, __shfl_xor_sync(0xffffffffu, am, o));
        }

        float l2 = sqrtf(ss);
        const float dim_scale = 0.03125f;                 // 1024^-0.5
        float fnorm  = dim_scale / fmaxf(l2, 1e-12f);
        float amax_n = am * fnorm;
        float scale  = 127.0f / fmaxf(amax_n, 1e-5f);
        float qf = fnorm * scale;

        int u = (lane & 15) >> 1;
        size_t rowoff = (size_t)m * 128 + (((u ^ (m & 7)) << 4) + (lane & 1) * 8);
#pragma unroll
        for (int i = 0; i < 8; i++) {
            float f0 = fminf(fmaxf(rintf(v[i].x * qf), -128.f), 127.f);
            float f1 = fminf(fmaxf(rintf(v[i].y * qf), -128.f), 127.f);
            float f2 = fminf(fmaxf(rintf(v[i].z * qf), -128.f), 127.f);
            float f3 = fminf(fmaxf(rintf(v[i].w * qf), -128.f), 127.f);
            __nv_bfloat162 p0, p1;
            p0.x = __float2bfloat16_rn(f0); p0.y = __float2bfloat16_rn(f1);
            p1.x = __float2bfloat16_rn(f2); p1.y = __float2bfloat16_rn(f3);
            uint2 pk;
            pk.x = *(uint32_t*)&p0; pk.y = *(uint32_t*)&p1;
            int c = 2 * i + (lane >> 4);
            *(uint2*)((char*)g_xb + (size_t)c * M * 128 + rowoff) = pk;
        }
        if (lane == 0) g_rdeq[m] = g_stats[2] / scale;
    } else if ((int)blockIdx.x < xblocks + 1024) {
        float wm = g_stats[0];
        int r = blockIdx.x - xblocks;       // weight row
        int t = threadIdx.x;
        float4 v = ((const float4*)w)[r * 256 + t];
        float f0 = (v.x > wm) ? 1.f : ((v.x < wm) ? -1.f : 0.f);
        float f1 = (v.y > wm) ? 1.f : ((v.y < wm) ? -1.f : 0.f);
        float f2 = (v.z > wm) ? 1.f : ((v.z < wm) ? -1.f : 0.f);
        float f3 = (v.w > wm) ? 1.f : ((v.w < wm) ? -1.f : 0.f);
        __nv_bfloat162 p0, p1;
        p0.x = __float2bfloat16_rn(f0); p0.y = __float2bfloat16_rn(f1);
        p1.x = __float2bfloat16_rn(f2); p1.y = __float2bfloat16_rn(f3);
        uint2 pk;
        pk.x = *(uint32_t*)&p0; pk.y = *(uint32_t*)&p1;
        int c = t >> 4;
        int u = (t & 15) >> 1;
        size_t dst = (size_t)(c * O_DIM + r) * 128 + (((u ^ (r & 7)) << 4) + (t & 1) * 8);
        *(uint2*)((char*)g_wb + dst) = pk;
    } else {
        float bm = g_stats[1];
        float4 v = ((const float4*)b)[threadIdx.x];
        float4 q;
        q.x = (v.x > bm) ? 1.f : ((v.x < bm) ? -1.f : 0.f);
        q.y = (v.y > bm) ? 1.f : ((v.y < bm) ? -1.f : 0.f);
        q.z = (v.z > bm) ? 1.f : ((v.z < bm) ? -1.f : 0.f);
        q.w = (v.w > bm) ? 1.f : ((v.w < bm) ? -1.f : 0.f);
        ((float4*)g_bq)[threadIdx.x] = q;
    }
}

// ---------------- fallback quant kernels (int8 path) ----------------
__global__ void quant_wb_kernel(const float* __restrict__ w, const float* __restrict__ b) {
    if (blockIdx.x < 1024) {
        float wm = g_stats[0];
        int idx = blockIdx.x * 256 + threadIdx.x;
        float4 v = ((const float4*)w)[idx];
        char4 q;
        q.x = (v.x > wm) ? 1 : ((v.x < wm) ? -1 : 0);
        q.y = (v.y > wm) ? 1 : ((v.y < wm) ? -1 : 0);
        q.z = (v.z > wm) ? 1 : ((v.z < wm) ? -1 : 0);
        q.w = (v.w > wm) ? 1 : ((v.w < wm) ? -1 : 0);
        ((char4*)g_wq)[idx] = q;
    } else {
        float bm = g_stats[1];
        float4 v = ((const float4*)b)[threadIdx.x];
        float4 q;
        q.x = (v.x > bm) ? 1.f : ((v.x < bm) ? -1.f : 0.f);
        q.y = (v.y > bm) ? 1.f : ((v.y < bm) ? -1.f : 0.f);
        q.z = (v.z > bm) ? 1.f : ((v.z < bm) ? -1.f : 0.f);
        q.w = (v.w > bm) ? 1.f : ((v.w < bm) ? -1.f : 0.f);
        ((float4*)g_bq)[threadIdx.x] = q;
    }
}

__global__ void quant_x_kernel(const float* __restrict__ x) {
    int warp = threadIdx.x >> 5, lane = threadIdx.x & 31;
    int m = blockIdx.x * 8 + warp;

    const float4* xr = (const float4*)(x + (size_t)m * D_DIM);
    float4 v[8];
    float ss = 0.f, am = 0.f;
#pragma unroll
    for (int i = 0; i < 8; i++) {
        v[i] = xr[lane + i * 32];
        ss += v[i].x * v[i].x + v[i].y * v[i].y + v[i].z * v[i].z + v[i].w * v[i].w;
        am = fmaxf(am, fmaxf(fmaxf(fabsf(v[i].x), fabsf(v[i].y)),
                             fmaxf(fabsf(v[i].z), fabsf(v[i].w))));
    }
#pragma unroll
    for (int o = 16; o; o >>= 1) {
        ss += __shfl_xor_sync(0xffffffffu, ss, o);
        am = fmaxf(am, __shfl_xor_sync(0xffffffffu, am, o));
    }

    float l2 = sqrtf(ss);
    const float dim_scale = 0.03125f;
    float fnorm  = dim_scale / fmaxf(l2, 1e-12f);
    float amax_n = am * fnorm;
    float scale  = 127.0f / fmaxf(amax_n, 1e-5f);
    float qf = fnorm * scale;

    char4* dst8 = (char4*)(g_xq + (size_t)m * D_DIM);
#pragma unroll
    for (int i = 0; i < 8; i++) {
        char4 q;
        q.x = (signed char)fminf(fmaxf(rintf(v[i].x * qf), -128.f), 127.f);
        q.y = (signed char)fminf(fmaxf(rintf(v[i].y * qf), -128.f), 127.f);
        q.z = (signed char)fminf(fmaxf(rintf(v[i].z * qf), -128.f), 127.f);
        q.w = (signed char)fminf(fmaxf(rintf(v[i].w * qf), -128.f), 127.f);
        dst8[lane + i * 32] = q;
    }
    if (lane == 0) g_rdeq[m] = g_stats[2] / scale;
}

// =================== common helpers ===================
__device__ __forceinline__ uint32_t smem_u32(const void* p) {
    uint32_t a;
    asm("{ .reg .u64 t; cvta.to.shared.u64 t, %1; cvt.u32.u64 %0, t; }" : "=r"(a) : "l"(p));
    return a;
}
__device__ __forceinline__ void cp16(uint32_t dst, const void* src) {
    asm volatile("cp.async.cg.shared.global [%0], [%1], 16;\n" :: "r"(dst), "l"(src));
}

// =================== stage 4A: legacy int8 mma GEMM (proven fallback) ===================
#define BM 128
#define BN 128
#define BK 64
#define SSTRIDE 80

__device__ __forceinline__ void mma_s8(int* c, const uint32_t* a, const uint32_t* b) {
    asm volatile(
        "mma.sync.aligned.m16n8k32.row.col.s32.s8.s8.s32 "
        "{%0,%1,%2,%3}, {%4,%5,%6,%7}, {%8,%9}, {%0,%1,%2,%3};\n"
        : "+r"(c[0]), "+r"(c[1]), "+r"(c[2]), "+r"(c[3])
        : "r"(a[0]), "r"(a[1]), "r"(a[2]), "r"(a[3]), "r"(b[0]), "r"(b[1]));
}

__global__ __launch_bounds__(256, 2) void gemm_kernel(float* __restrict__ out, int M) {
    __shared__ int8_t sA[2][BM * SSTRIDE];
    __shared__ int8_t sB[2][BN * SSTRIDE];

    int tid = threadIdx.x;
    int m0 = blockIdx.y * BM;
    int n0 = blockIdx.x * BN;

    const int8_t* Aptr = g_xq + (size_t)m0 * D_DIM;
    const int8_t* Bptr = g_wq + (size_t)n0 * D_DIM;

    uint32_t sA_base = smem_u32(sA);
    uint32_t sB_base = smem_u32(sB);

    int warp = tid >> 5, lane = tid & 31;
    int wm = warp >> 2, wn = warp & 3;
    int rbase = wm * 64, cbase = wn * 32;
    int g = lane >> 2, j = lane & 3;

    int acc[4][4][4];
#pragma unroll
    for (int i = 0; i < 4; i++)
#pragma unroll
        for (int nf = 0; nf < 4; nf++)
#pragma unroll
            for (int r = 0; r < 4; r++) acc[i][nf][r] = 0;

    const int NS = D_DIM / BK;

    {
#pragma unroll
        for (int l = 0; l < 2; l++) {
            int c = tid + l * 256;
            int row = c >> 2, off = (c & 3) << 4;
            cp16(sA_base + row * SSTRIDE + off, Aptr + (size_t)row * D_DIM + off);
            cp16(sB_base + row * SSTRIDE + off, Bptr + (size_t)row * D_DIM + off);
        }
        asm volatile("cp.async.commit_group;\n");
    }

    for (int s = 0; s < NS; s++) {
        int buf = s & 1;
        if (s + 1 < NS) {
            int nbuf = buf ^ 1;
            int k0 = (s + 1) * BK;
#pragma unroll
            for (int l = 0; l < 2; l++) {
                int c = tid + l * 256;
                int row = c >> 2, off = (c & 3) << 4;
                cp16(sA_base + nbuf * (BM * SSTRIDE) + row * SSTRIDE + off,
                     Aptr + (size_t)row * D_DIM + k0 + off);
                cp16(sB_base + nbuf * (BN * SSTRIDE) + row * SSTRIDE + off,
                     Bptr + (size_t)row * D_DIM + k0 + off);
            }
            asm volatile("cp.async.commit_group;\n");
            asm volatile("cp.async.wait_group 1;\n");
        } else {
            asm volatile("cp.async.wait_group 0;\n");
        }
        __syncthreads();

        const int8_t* sAb = sA[buf];
        const int8_t* sBb = sB[buf];
#pragma unroll
        for (int kk = 0; kk < 2; kk++) {
            uint32_t a[4][4];
#pragma unroll
            for (int i = 0; i < 4; i++) {
                const int8_t* base = sAb + (rbase + i * 16 + g) * SSTRIDE + kk * 32 + j * 4;
                a[i][0] = *(const uint32_t*)(base);
                a[i][1] = *(const uint32_t*)(base + 8 * SSTRIDE);
                a[i][2] = *(const uint32_t*)(base + 16);
                a[i][3] = *(const uint32_t*)(base + 8 * SSTRIDE + 16);
            }
            uint32_t bb[4][2];
#pragma unroll
            for (int nf = 0; nf < 4; nf++) {
                const int8_t* base = sBb + (cbase + nf * 8 + g) * SSTRIDE + kk * 32 + j * 4;
                bb[nf][0] = *(const uint32_t*)(base);
                bb[nf][1] = *(const uint32_t*)(base + 16);
            }
#pragma unroll
            for (int i = 0; i < 4; i++)
#pragma unroll
                for (int nf = 0; nf < 4; nf++)
                    mma_s8(acc[i][nf], a[i], bb[nf]);
        }
        __syncthreads();
    }

#pragma unroll
    for (int i = 0; i < 4; i++) {
        int r0 = m0 + rbase + i * 16 + g;
        float rd0 = g_rdeq[r0];
        float rd1 = g_rdeq[r0 + 8];
#pragma unroll
        for (int nf = 0; nf < 4; nf++) {
            int cc = n0 + cbase + nf * 8 + j * 2;
            float b0v = g_bq[cc], b1v = g_bq[cc + 1];
            float2 v0, v1;
            v0.x = ((float)acc[i][nf][0] + b0v) * rd0;
            v0.y = ((float)acc[i][nf][1] + b1v) * rd0;
            v1.x = ((float)acc[i][nf][2] + b0v) * rd1;
            v1.y = ((float)acc[i][nf][3] + b1v) * rd1;
            *(float2*)&out[(size_t)r0 * O_DIM + cc]        = v0;
            *(float2*)&out[(size_t)(r0 + 8) * O_DIM + cc]  = v1;
        }
    }
}

// =================== stage 4B: persistent tcgen05 bf16 GEMM ===================
// Cluster-4 (ranks = n-tiles of one m-band); A multicast once per cluster by the
// DECOUPLED producer warp (handshake latency hidden by 3-slot depth).
// 128 persistent CTAs x 4 tiles (256x256), 288 threads:
//   warps 0-7 : epilogue workers (tid0 additionally issues MMAs)
//   warp 8    : copy producer — continuous 64-chunk stream (B local, A multicast)
#define TILE_M 256
#define TILE_N 256
#define SLOT_BYTES 65536        // A 32KB + B 32KB
#define NSLOT 3
#define NPCTA 128
#define NTPC 4                  // tiles per CTA
#define CLSZ 4
#define SM_TMEM      0
#define SM_MB_FULL   8          // 3 x 8B
#define SM_MB_EMPTY  32         // 3 x 8B
#define SM_MB_DONE   56
#define SM_MB_EPIFREE 64
#define SM_MB_READY  72         // 3 x 8B (meaningful on rank0)
#define SM_BIAS      1024       // 256 floats
#define SM_TP        2048       // 8 warps x 32x33 floats = 33792B
#define SM_TILES     35840      // 1024-aligned, after TP
#define SMEM_TOTAL_GEMM (SM_TILES + NSLOT * SLOT_BYTES)   // 232448

#if defined(__CUDA_ARCH__) && (defined(__CUDA_ARCH_SPECIFIC__) || defined(__CUDA_ARCH_FAMILY_SPECIFIC__))
#define HAS_TCGEN05 1
#else
#define HAS_TCGEN05 0
#endif

#if HAS_TCGEN05
// SW128 K-major smem descriptor (LBO=1, SBO=64, version=1, layout=SW128)
static __device__ __forceinline__ uint64_t make_desc(uint32_t addr) {
    const uint64_t base = (2ULL << 61) | (1ULL << 46) | (64ULL << 32) | (1ULL << 16);
    return base | ((uint64_t)(addr >> 4) & 0x3FFF);
}

// idesc kind::f16: dtype=F32(1)<<4, atype=BF16(1)<<7, btype=BF16(1)<<10, N/8<<17, M/16<<24
#define IDESC_BF16 ((1u << 4) | (1u << 7) | (1u << 10) | ((TILE_N / 8) << 17) | ((128 / 16) << 24))

__device__ __forceinline__ void mma_bf16_ss(uint32_t d_tmem, uint64_t a_desc, uint64_t b_desc,
                                            uint32_t idesc, uint32_t enable) {
    asm volatile(
        "{\n\t.reg .pred p;\n\t"
        "setp.ne.u32 p, %5, 0;\n\t"
        "tcgen05.mma.cta_group::1.kind::f16 [%0], %1, %2, %3, {%4, %4, %4, %4}, p;\n\t}"
        :: "r"(d_tmem), "l"(a_desc), "l"(b_desc), "r"(idesc), "r"(0u), "r"(enable)
        : "memory");
}

__device__ __forceinline__ void bulk_cp(uint32_t dst, const void* src, uint32_t bytes,
                                        uint32_t mbar) {
    asm volatile(
        "cp.async.bulk.shared::cluster.global.mbarrier::complete_tx::bytes [%0], [%1], %2, [%3];"
        :: "r"(dst), "l"(src), "r"(bytes), "r"(mbar) : "memory");
}

// multicast bulk copy: data + complete_tx to the same smem offset in every
// cluster CTA whose bit is set in mask
__device__ __forceinline__ void bulk_cp_mc(uint32_t dst, const void* src, uint32_t bytes,
                                           uint32_t mbar, uint16_t mask) {
    asm volatile(
        "cp.async.bulk.shared::cluster.global.mbarrier::complete_tx::bytes.multicast::cluster "
        "[%0], [%1], %2, [%3], %4;"
        :: "r"(dst), "l"(src), "r"(bytes), "r"(mbar), "h"(mask) : "memory");
}

__device__ __forceinline__ uint32_t cluster_rank() {
    uint32_t r;
    asm("mov.u32 %0, %%cluster_ctarank;" : "=r"(r));
    return r;
}

__device__ __forceinline__ void arrive_rank0(uint32_t local_addr) {
    asm volatile(
        "{\n\t.reg .b32 ra;\n\t"
        "mapa.shared::cluster.u32 ra, %0, 0;\n\t"
        "mbarrier.arrive.shared::cluster.b64 _, [ra];\n\t}"
        :: "r"(local_addr) : "memory");
}

#define CLUSTER_SYNC_() do { \
    asm volatile("barrier.cluster.arrive.aligned;" ::: "memory"); \
    asm volatile("barrier.cluster.wait.aligned;" ::: "memory"); \
} while (0)

#define MBAR_INIT(addr, cnt) \
    asm volatile("mbarrier.init.shared.b64 [%0], %1;" :: "r"(addr), "r"(cnt) : "memory")

#define MBAR_EXPECT_TX(addr, tx) \
    asm volatile("mbarrier.arrive.expect_tx.shared.b64 _, [%0], %1;" :: "r"(addr), "r"(tx) : "memory")

#define MBAR_ARRIVE(addr) \
    asm volatile("mbarrier.arrive.shared.b64 _, [%0];" :: "r"(addr) : "memory")

#define MBAR_WAIT(addr, ph) do {                                              \
    asm volatile(                                                             \
        "{\n\t.reg .pred P;\n\t"                                              \
        "W%=:\n\t"                                                            \
        "mbarrier.try_wait.parity.acquire.cta.shared::cta.b64 P, [%0], %1, 0x989680;\n\t" \
        "@P bra.uni D%=;\n\t"                                                 \
        "bra.uni W%=;\n\t"                                                    \
        "D%=:\n\t}"                                                           \
        :: "r"(addr), "r"(ph) : "memory");                                    \
} while (0)

#define TC_COMMIT(addr) \
    asm volatile("tcgen05.commit.cta_group::1.mbarrier::arrive::one.shared::cluster.b64 [%0];" \
                 :: "r"(addr) : "memory")

#define TCWAIT_LD() asm volatile("tcgen05.wait::ld.sync.aligned;" ::: "memory")

#define LDTM_X32(r, addr) \
    asm volatile( \
        "tcgen05.ld.sync.aligned.32x32b.x32.b32 " \
        "{%0,%1,%2,%3,%4,%5,%6,%7,%8,%9,%10,%11,%12,%13,%14,%15," \
        "%16,%17,%18,%19,%20,%21,%22,%23,%24,%25,%26,%27,%28,%29,%30,%31}, [%32];" \
        : "=r"((r)[0]),  "=r"((r)[1]),  "=r"((r)[2]),  "=r"((r)[3]), \
          "=r"((r)[4]),  "=r"((r)[5]),  "=r"((r)[6]),  "=r"((r)[7]), \
          "=r"((r)[8]),  "=r"((r)[9]),  "=r"((r)[10]), "=r"((r)[11]), \
          "=r"((r)[12]), "=r"((r)[13]), "=r"((r)[14]), "=r"((r)[15]), \
          "=r"((r)[16]), "=r"((r)[17]), "=r"((r)[18]), "=r"((r)[19]), \
          "=r"((r)[20]), "=r"((r)[21]), "=r"((r)[22]), "=r"((r)[23]), \
          "=r"((r)[24]), "=r"((r)[25]), "=r"((r)[26]), "=r"((r)[27]), \
          "=r"((r)[28]), "=r"((r)[29]), "=r"((r)[30]), "=r"((r)[31]) \
        : "r"(addr))

// process one 32-col chunk: bias+dequant -> warp transpose -> coalesced stores
#define EPI_PROC(d, cb) do {                                                         \
    _Pragma("unroll")                                                                \
    for (int k_ = 0; k_ < 32; k_++)                                                  \
        tp[lane * 33 + k_] = (__uint_as_float((d)[k_]) + sbias[(cb) * 32 + k_]) * rd; \
    __syncwarp();                                                                    \
    _Pragma("unroll")                                                                \
    for (int r_ = 0; r_ < 32; r_++)                                                  \
        out[(size_t)(rowbase + r_) * O_DIM + n0 + (cb) * 32 + lane] = tp[r_ * 33 + lane]; \
    __syncwarp();                                                                    \
} while (0)
#endif  // HAS_TCGEN05

__global__ void __launch_bounds__(288, 1) __cluster_dims__(CLSZ, 1, 1)
gemm_tc_kernel(float* __restrict__ out, int M) {
#if HAS_TCGEN05
    extern __shared__ __align__(1024) char smem[];
    uint32_t sbase = smem_u32(smem);
    int tid = threadIdx.x;
    int wid = tid >> 5, lane = tid & 31;

    const int TOTC = NTPC * NCHUNK;   // 64 chunks per CTA

    if (wid == 0) {
        asm volatile("tcgen05.alloc.cta_group::1.sync.aligned.shared::cta.b32 [%0], %1;"
                     :: "r"(sbase + SM_TMEM), "r"(512) : "memory");
        asm volatile("tcgen05.relinquish_alloc_permit.cta_group::1.sync.aligned;");
    }
    if (tid == 0) {
#pragma unroll
        for (int i = 0; i < NSLOT; i++) {
            MBAR_INIT(sbase + SM_MB_FULL + i * 8, 1);
            MBAR_INIT(sbase + SM_MB_EMPTY + i * 8, 1);
            MBAR_INIT(sbase + SM_MB_READY + i * 8, CLSZ);
        }
        MBAR_INIT(sbase + SM_MB_DONE, 1);
        MBAR_INIT(sbase + SM_MB_EPIFREE, 256);
    }
    // bias staged ONCE: n0 fixed per CTA (= rank * TILE_N)
    int n0 = ((int)blockIdx.x & 3) * TILE_N;
    if (tid < 256) ((float*)(smem + SM_BIAS))[tid] = g_bq[n0 + tid];
    __syncthreads();
    CLUSTER_SYNC_();   // all cluster barriers initialized before any multicast

    uint32_t tmem_base;
    asm volatile("ld.shared.b32 %0, [%1];" : "=r"(tmem_base) : "r"(sbase + SM_TMEM));

    const char* abase = (const char*)g_xb;
    const char* bbase = (const char*)g_wb;

    if (wid == 8) {
        // ============ copy producer: continuous 64-chunk stream ============
        // Each CTA: expect_tx(64KB) -> local B copy -> arrive rank0's ready.
        // Rank0: after all 4 ready arrivals, multicast A chunk to the cluster.
        if (lane == 0) {
            unsigned eph = 0, rph = 0;
            uint32_t rank = cluster_rank();
            for (int g = 0; g < TOTC; g++) {
                int slot = g % NSLOT;
                if (g >= NSLOT) {
                    uint32_t eb = sbase + SM_MB_EMPTY + slot * 8;
                    MBAR_WAIT(eb, (eph >> slot) & 1);
                    eph ^= (1u << slot);
                }
                int gt = blockIdx.x + (g >> 4) * NPCTA;
                int m0 = (gt >> 2) * TILE_M;          // same across cluster ranks
                int ck = g & 15;
                uint32_t fb = sbase + SM_MB_FULL + slot * 8;
                uint32_t sl = sbase + SM_TILES + slot * SLOT_BYTES;
                MBAR_EXPECT_TX(fb, (uint32_t)SLOT_BYTES);
                bulk_cp(sl + 32768, bbase + ((size_t)ck * O_DIM + n0) * 128, 32768, fb);
                arrive_rank0(sbase + SM_MB_READY + slot * 8);
                if (rank == 0) {
                    MBAR_WAIT(sbase + SM_MB_READY + slot * 8, (rph >> slot) & 1);
                    rph ^= (1u << slot);
                    bulk_cp_mc(sl, abase + ((size_t)ck * M + m0) * 128, 32768, fb, 0xF);
                }
            }
        }
    } else {
        // ============ MMA issuer (tid0) + epilogue warps 0-7 ============
        const float* sbias = (const float*)(smem + SM_BIAS);
        float* tp = (float*)(smem + SM_TP) + wid * (32 * 33);
        unsigned fph = 0;
        int dph = 0, efph = 0;
        int eh = wid >> 2;          // M-half
        int esp = wid & 3;          // 32-row subpartition

        for (int tl = 0; tl < NTPC; tl++) {
            int gt = blockIdx.x + tl * NPCTA;
            int m0 = (gt >> 2) * TILE_M;

            if (tid == 0) {
                if (tl > 0) {
                    MBAR_WAIT(sbase + SM_MB_EPIFREE, efph);
                    efph ^= 1;
                    asm volatile("tcgen05.fence::after_thread_sync;" ::: "memory");
                }
                for (int s = 0; s < NCHUNK; s++) {
                    int g = tl * NCHUNK + s;
                    int slot = g % NSLOT;
                    uint32_t fb = sbase + SM_MB_FULL + slot * 8;
                    uint32_t sl = sbase + SM_TILES + slot * SLOT_BYTES;

                    MBAR_WAIT(fb, (fph >> slot) & 1);
                    fph ^= (1u << slot);

                    uint64_t a_base = make_desc(sl);
                    uint64_t b_base = make_desc(sl + 32768);
#pragma unroll
                    for (int h = 0; h < 2; h++) {
#pragma unroll
                        for (int k = 0; k < 4; k++) {
                            mma_bf16_ss(tmem_base + h * TILE_N,
                                        a_base + h * 1024 + k * 2,
                                        b_base + k * 2,
                                        IDESC_BF16,
                                        (s > 0 || k > 0) ? 1u : 0u);
                        }
                    }
                    if (g + NSLOT < TOTC) {
                        TC_COMMIT(sbase + SM_MB_EMPTY + slot * 8);
                    }
                }
                TC_COMMIT(sbase + SM_MB_DONE);
            }

            // all epilogue threads wait for this tile's MMAs to retire
            MBAR_WAIT(sbase + SM_MB_DONE, dph);
            dph ^= 1;
            asm volatile("tcgen05.fence::after_thread_sync;" ::: "memory");

            // epilogue: software-pipelined LDTM pairs
            {
                int rowbase = m0 + eh * 128 + esp * 32;
                float rd = g_rdeq[rowbase + lane];
                uint32_t tb = tmem_base + eh * TILE_N;
                uint32_t da[32], db[32], dc[32], dd[32];

                LDTM_X32(da, tb);       LDTM_X32(db, tb + 32);
                TCWAIT_LD();
                LDTM_X32(dc, tb + 64);  LDTM_X32(dd, tb + 96);
                EPI_PROC(da, 0);        EPI_PROC(db, 1);
                TCWAIT_LD();
                LDTM_X32(da, tb + 128); LDTM_X32(db, tb + 160);
                EPI_PROC(dc, 2);        EPI_PROC(dd, 3);
                TCWAIT_LD();
                LDTM_X32(dc, tb + 192); LDTM_X32(dd, tb + 224);
                EPI_PROC(da, 4);        EPI_PROC(db, 5);
                TCWAIT_LD();
                EPI_PROC(dc, 6);        EPI_PROC(dd, 7);
            }
            asm volatile("tcgen05.fence::before_thread_sync;" ::: "memory");
            MBAR_ARRIVE(sbase + SM_MB_EPIFREE);
        }
    }

    __syncthreads();
    CLUSTER_SYNC_();   // no CTA exits while a multicast targeting it may be in flight
    if (wid == 0) {
        asm volatile("tcgen05.dealloc.cta_group::1.sync.aligned.b32 %0, %1;"
                     :: "r"(tmem_base), "r"(512));
    }
#else
    (void)out; (void)M;   // base-arch pass: stub (never launched)
#endif
}

// ---------------- launch ----------------
extern "C" void kernel_launch(void* const* d_in, const int* in_sizes, int n_in,
                              void* d_out, int out_size) {
    const float* x = (const float*)d_in[0];
    const float* w = (const float*)d_in[1];
    const float* b = (const float*)d_in[2];
    float* out = (float*)d_out;

    int M = in_sizes[0] / D_DIM;   // 32768

    cudaFuncAttributes fa;
    bool has_tc = false;
    if (cudaFuncGetAttributes(&fa, (const void*)gemm_tc_kernel) == cudaSuccess)
        has_tc = (fa.numRegs >= 32);

    stats_part_kernel<<<1025, 256>>>(w, b);
    stats_final_kernel<<<1, 1024>>>();

    if (has_tc) {
        quant_fused_tc_kernel<<<M / 8 + 1025, 256>>>(x, w, b, M);
        cudaFuncSetAttribute(gemm_tc_kernel,
                             cudaFuncAttributeMaxDynamicSharedMemorySize, SMEM_TOTAL_GEMM);
        gemm_tc_kernel<<<NPCTA, 288, SMEM_TOTAL_GEMM>>>(out, M);
    } else {
        quant_wb_kernel<<<1025, 256>>>(w, b);
        quant_x_kernel<<<M / 8, 256>>>(x);
        dim3 grid(O_DIM / BN, M / BM);
        gemm_kernel<<<grid, 256>>>(out, M);
    }
}

// round 17
// speedup vs baseline: 1.0539x; 1.0539x over previous
#include <cuda_runtime.h>
#include <cuda_bf16.h>
#include <cstdint>
#include <cstddef>

// Problem dims (fixed by the dataset): x [4,8192,1024], w [1024,1024], b [1024]
#define D_DIM 1024
#define O_DIM 1024
#define M_MAX 32768
#define NCHUNK 16               // K chunks of 64 bf16 (128B rows)

// ---------------- device scratch (no allocations allowed) ----------------
__device__ int8_t        g_xq[(size_t)M_MAX * D_DIM];   // int8 activations (fallback)
__device__ __nv_bfloat16 g_xb[(size_t)M_MAX * D_DIM];   // bf16 acts, chunk-major + SW128-swizzled
__device__ float         g_rdeq[M_MAX];                 // per-token dequant multiplier
__device__ int8_t        g_wq[(size_t)O_DIM * D_DIM];   // ternary weights int8 (fallback)
__device__ __nv_bfloat16 g_wb[(size_t)O_DIM * D_DIM];   // bf16 weights, chunk-major + swizzled
__device__ float         g_bq[O_DIM];                   // ternary bias as float
__device__ float         g_stats[4];                    // [0]=w_mean [1]=b_mean [2]=1/(ws*bs)
__device__ double2       g_part[1025];                  // per-row partials; [1024] = bias
__device__ unsigned      g_ticket = 0;                  // last-block ticket (self-resetting)

// ---------------- stage 1: fused stats (partials + last-block final reduce) ----------------
__global__ void stats_kernel(const float* __restrict__ w, const float* __restrict__ b) {
    int blk = blockIdx.x;   // 0..1023 -> w row blk ; 1024 -> bias
    int t = threadIdx.x;    // 256 threads, one float4 each
    int warp = t >> 5, lane = t & 31;

    float4 v;
    if (blk < 1024) v = ((const float4*)w)[blk * 256 + t];
    else            v = ((const float4*)b)[t];

    double s  = (double)v.x + (double)v.y + (double)v.z + (double)v.w;
    double sa = fabs((double)v.x) + fabs((double)v.y) + fabs((double)v.z) + fabs((double)v.w);

    for (int o = 16; o; o >>= 1) {
        s  += __shfl_xor_sync(0xffffffffu, s,  o);
        sa += __shfl_xor_sync(0xffffffffu, sa, o);
    }
    __shared__ double sh[8][2];
    if (lane == 0) { sh[warp][0] = s; sh[warp][1] = sa; }
    __syncthreads();
    __shared__ bool isLast;
    if (t == 0) {
        double S = 0, SA = 0;
#pragma unroll
        for (int i = 0; i < 8; i++) { S += sh[i][0]; SA += sh[i][1]; }
        g_part[blk] = make_double2(S, SA);
        __threadfence();
        unsigned old = atomicInc(&g_ticket, 1024);   // wraps to 0 after the 1025th
        isLast = (old == 1024);
    }
    __syncthreads();

    if (isLast) {
        __threadfence();   // acquire all blocks' g_part writes
        // fixed-order deterministic reduce of the 1024 w-partials: thread t
        // sums partials t, t+256, t+512, t+768
        double s2 = 0, sa2 = 0;
#pragma unroll
        for (int k = 0; k < 4; k++) {
            double2 p = g_part[t + k * 256];
            s2 += p.x; sa2 += p.y;
        }
        for (int o = 16; o; o >>= 1) {
            s2  += __shfl_xor_sync(0xffffffffu, s2,  o);
            sa2 += __shfl_xor_sync(0xffffffffu, sa2, o);
        }
        __shared__ double sh2[8][2];
        if (lane == 0) { sh2[warp][0] = s2; sh2[warp][1] = sa2; }
        __syncthreads();
        if (t == 0) {
            double S = 0, SA = 0;
#pragma unroll
            for (int i = 0; i < 8; i++) { S += sh2[i][0]; SA += sh2[i][1]; }
            double2 bp = g_part[1024];
            double w_mean  = S  / (double)(O_DIM * D_DIM);
            double w_scale = SA / (double)(O_DIM * D_DIM);
            double b_mean  = bp.x / (double)O_DIM;
            double b_scale = bp.y / (double)O_DIM;
            g_stats[0] = (float)w_mean;
            g_stats[1] = (float)b_mean;
            g_stats[2] = (float)(1.0 / (w_scale * b_scale));
        }
    }
}

// ---------------- stage 2+3 (tc path, fused): quant x AND w/b in one launch ----------------
__global__ void quant_fused_tc_kernel(const float* __restrict__ x,
                                      const float* __restrict__ w,
                                      const float* __restrict__ b, int M) {
    int xblocks = M >> 3;
    if ((int)blockIdx.x < xblocks) {
        int warp = threadIdx.x >> 5, lane = threadIdx.x & 31;
        int m = blockIdx.x * 8 + warp;

        const float4* xr = (const float4*)(x + (size_t)m * D_DIM);
        float4 v[8];
        float ss = 0.f, am = 0.f;
#pragma unroll
        for (int i = 0; i < 8; i++) {
            v[i] = xr[lane + i * 32];
            ss += v[i].x * v[i].x + v[i].y * v[i].y + v[i].z * v[i].z + v[i].w * v[i].w;
            am = fmaxf(am, fmaxf(fmaxf(fabsf(v[i].x), fabsf(v[i].y)),
                                 fmaxf(fabsf(v[i].z), fabsf(v[i].w))));
        }
#pragma unroll
        for (int o = 16; o; o >>= 1) {
            ss += __shfl_xor_sync(0xffffffffu, ss, o);
            am = fmaxf(am, __shfl_xor_sync(0xffffffffu, am, o));
        }

        float l2 = sqrtf(ss);
        const float dim_scale = 0.03125f;                 // 1024^-0.5
        float fnorm  = dim_scale / fmaxf(l2, 1e-12f);
        float amax_n = am * fnorm;
        float scale  = 127.0f / fmaxf(amax_n, 1e-5f);
        float qf = fnorm * scale;

        int u = (lane & 15) >> 1;
        size_t rowoff = (size_t)m * 128 + (((u ^ (m & 7)) << 4) + (lane & 1) * 8);
#pragma unroll
        for (int i = 0; i < 8; i++) {
            float f0 = fminf(fmaxf(rintf(v[i].x * qf), -128.f), 127.f);
            float f1 = fminf(fmaxf(rintf(v[i].y * qf), -128.f), 127.f);
            float f2 = fminf(fmaxf(rintf(v[i].z * qf), -128.f), 127.f);
            float f3 = fminf(fmaxf(rintf(v[i].w * qf), -128.f), 127.f);
            __nv_bfloat162 p0, p1;
            p0.x = __float2bfloat16_rn(f0); p0.y = __float2bfloat16_rn(f1);
            p1.x = __float2bfloat16_rn(f2); p1.y = __float2bfloat16_rn(f3);
            uint2 pk;
            pk.x = *(uint32_t*)&p0; pk.y = *(uint32_t*)&p1;
            int c = 2 * i + (lane >> 4);
            *(uint2*)((char*)g_xb + (size_t)c * M * 128 + rowoff) = pk;
        }
        if (lane == 0) g_rdeq[m] = g_stats[2] / scale;
    } else if ((int)blockIdx.x < xblocks + 1024) {
        float wm = g_stats[0];
        int r = blockIdx.x - xblocks;       // weight row
        int t = threadIdx.x;
        float4 v = ((const float4*)w)[r * 256 + t];
        float f0 = (v.x > wm) ? 1.f : ((v.x < wm) ? -1.f : 0.f);
        float f1 = (v.y > wm) ? 1.f : ((v.y < wm) ? -1.f : 0.f);
        float f2 = (v.z > wm) ? 1.f : ((v.z < wm) ? -1.f : 0.f);
        float f3 = (v.w > wm) ? 1.f : ((v.w < wm) ? -1.f : 0.f);
        __nv_bfloat162 p0, p1;
        p0.x = __float2bfloat16_rn(f0); p0.y = __float2bfloat16_rn(f1);
        p1.x = __float2bfloat16_rn(f2); p1.y = __float2bfloat16_rn(f3);
        uint2 pk;
        pk.x = *(uint32_t*)&p0; pk.y = *(uint32_t*)&p1;
        int c = t >> 4;
        int u = (t & 15) >> 1;
        size_t dst = (size_t)(c * O_DIM + r) * 128 + (((u ^ (r & 7)) << 4) + (t & 1) * 8);
        *(uint2*)((char*)g_wb + dst) = pk;
    } else {
        float bm = g_stats[1];
        float4 v = ((const float4*)b)[threadIdx.x];
        float4 q;
        q.x = (v.x > bm) ? 1.f : ((v.x < bm) ? -1.f : 0.f);
        q.y = (v.y > bm) ? 1.f : ((v.y < bm) ? -1.f : 0.f);
        q.z = (v.z > bm) ? 1.f : ((v.z < bm) ? -1.f : 0.f);
        q.w = (v.w > bm) ? 1.f : ((v.w < bm) ? -1.f : 0.f);
        ((float4*)g_bq)[threadIdx.x] = q;
    }
}

// ---------------- fallback quant kernels (int8 path) ----------------
__global__ void quant_wb_kernel(const float* __restrict__ w, const float* __restrict__ b) {
    if (blockIdx.x < 1024) {
        float wm = g_stats[0];
        int idx = blockIdx.x * 256 + threadIdx.x;
        float4 v = ((const float4*)w)[idx];
        char4 q;
        q.x = (v.x > wm) ? 1 : ((v.x < wm) ? -1 : 0);
        q.y = (v.y > wm) ? 1 : ((v.y < wm) ? -1 : 0);
        q.z = (v.z > wm) ? 1 : ((v.z < wm) ? -1 : 0);
        q.w = (v.w > wm) ? 1 : ((v.w < wm) ? -1 : 0);
        ((char4*)g_wq)[idx] = q;
    } else {
        float bm = g_stats[1];
        float4 v = ((const float4*)b)[threadIdx.x];
        float4 q;
        q.x = (v.x > bm) ? 1.f : ((v.x < bm) ? -1.f : 0.f);
        q.y = (v.y > bm) ? 1.f : ((v.y < bm) ? -1.f : 0.f);
        q.z = (v.z > bm) ? 1.f : ((v.z < bm) ? -1.f : 0.f);
        q.w = (v.w > bm) ? 1.f : ((v.w < bm) ? -1.f : 0.f);
        ((float4*)g_bq)[threadIdx.x] = q;
    }
}

__global__ void quant_x_kernel(const float* __restrict__ x) {
    int warp = threadIdx.x >> 5, lane = threadIdx.x & 31;
    int m = blockIdx.x * 8 + warp;

    const float4* xr = (const float4*)(x + (size_t)m * D_DIM);
    float4 v[8];
    float ss = 0.f, am = 0.f;
#pragma unroll
    for (int i = 0; i < 8; i++) {
        v[i] = xr[lane + i * 32];
        ss += v[i].x * v[i].x + v[i].y * v[i].y + v[i].z * v[i].z + v[i].w * v[i].w;
        am = fmaxf(am, fmaxf(fmaxf(fabsf(v[i].x), fabsf(v[i].y)),
                             fmaxf(fabsf(v[i].z), fabsf(v[i].w))));
    }
#pragma unroll
    for (int o = 16; o; o >>= 1) {
        ss += __shfl_xor_sync(0xffffffffu, ss, o);
        am = fmaxf(am, __shfl_xor_sync(0xffffffffu, am, o));
    }

    float l2 = sqrtf(ss);
    const float dim_scale = 0.03125f;
    float fnorm  = dim_scale / fmaxf(l2, 1e-12f);
    float amax_n = am * fnorm;
    float scale  = 127.0f / fmaxf(amax_n, 1e-5f);
    float qf = fnorm * scale;

    char4* dst8 = (char4*)(g_xq + (size_t)m * D_DIM);
#pragma unroll
    for (int i = 0; i < 8; i++) {
        char4 q;
        q.x = (signed char)fminf(fmaxf(rintf(v[i].x * qf), -128.f), 127.f);
        q.y = (signed char)fminf(fmaxf(rintf(v[i].y * qf), -128.f), 127.f);
        q.z = (signed char)fminf(fmaxf(rintf(v[i].z * qf), -128.f), 127.f);
        q.w = (signed char)fminf(fmaxf(rintf(v[i].w * qf), -128.f), 127.f);
        dst8[lane + i * 32] = q;
    }
    if (lane == 0) g_rdeq[m] = g_stats[2] / scale;
}

// =================== common helpers ===================
__device__ __forceinline__ uint32_t smem_u32(const void* p) {
    uint32_t a;
    asm("{ .reg .u64 t; cvta.to.shared.u64 t, %1; cvt.u32.u64 %0, t; }" : "=r"(a) : "l"(p));
    return a;
}
__device__ __forceinline__ void cp16(uint32_t dst, const void* src) {
    asm volatile("cp.async.cg.shared.global [%0], [%1], 16;\n" :: "r"(dst), "l"(src));
}

// =================== stage 4A: legacy int8 mma GEMM (proven fallback) ===================
#define BM 128
#define BN 128
#define BK 64
#define SSTRIDE 80

__device__ __forceinline__ void mma_s8(int* c, const uint32_t* a, const uint32_t* b) {
    asm volatile(
        "mma.sync.aligned.m16n8k32.row.col.s32.s8.s8.s32 "
        "{%0,%1,%2,%3}, {%4,%5,%6,%7}, {%8,%9}, {%0,%1,%2,%3};\n"
        : "+r"(c[0]), "+r"(c[1]), "+r"(c[2]), "+r"(c[3])
        : "r"(a[0]), "r"(a[1]), "r"(a[2]), "r"(a[3]), "r"(b[0]), "r"(b[1]));
}

__global__ __launch_bounds__(256, 2) void gemm_kernel(float* __restrict__ out, int M) {
    __shared__ int8_t sA[2][BM * SSTRIDE];
    __shared__ int8_t sB[2][BN * SSTRIDE];

    int tid = threadIdx.x;
    int m0 = blockIdx.y * BM;
    int n0 = blockIdx.x * BN;

    const int8_t* Aptr = g_xq + (size_t)m0 * D_DIM;
    const int8_t* Bptr = g_wq + (size_t)n0 * D_DIM;

    uint32_t sA_base = smem_u32(sA);
    uint32_t sB_base = smem_u32(sB);

    int warp = tid >> 5, lane = tid & 31;
    int wm = warp >> 2, wn = warp & 3;
    int rbase = wm * 64, cbase = wn * 32;
    int g = lane >> 2, j = lane & 3;

    int acc[4][4][4];
#pragma unroll
    for (int i = 0; i < 4; i++)
#pragma unroll
        for (int nf = 0; nf < 4; nf++)
#pragma unroll
            for (int r = 0; r < 4; r++) acc[i][nf][r] = 0;

    const int NS = D_DIM / BK;

    {
#pragma unroll
        for (int l = 0; l < 2; l++) {
            int c = tid + l * 256;
            int row = c >> 2, off = (c & 3) << 4;
            cp16(sA_base + row * SSTRIDE + off, Aptr + (size_t)row * D_DIM + off);
            cp16(sB_base + row * SSTRIDE + off, Bptr + (size_t)row * D_DIM + off);
        }
        asm volatile("cp.async.commit_group;\n");
    }

    for (int s = 0; s < NS; s++) {
        int buf = s & 1;
        if (s + 1 < NS) {
            int nbuf = buf ^ 1;
            int k0 = (s + 1) * BK;
#pragma unroll
            for (int l = 0; l < 2; l++) {
                int c = tid + l * 256;
                int row = c >> 2, off = (c & 3) << 4;
                cp16(sA_base + nbuf * (BM * SSTRIDE) + row * SSTRIDE + off,
                     Aptr + (size_t)row * D_DIM + k0 + off);
                cp16(sB_base + nbuf * (BN * SSTRIDE) + row * SSTRIDE + off,
                     Bptr + (size_t)row * D_DIM + k0 + off);
            }
            asm volatile("cp.async.commit_group;\n");
            asm volatile("cp.async.wait_group 1;\n");
        } else {
            asm volatile("cp.async.wait_group 0;\n");
        }
        __syncthreads();

        const int8_t* sAb = sA[buf];
        const int8_t* sBb = sB[buf];
#pragma unroll
        for (int kk = 0; kk < 2; kk++) {
            uint32_t a[4][4];
#pragma unroll
            for (int i = 0; i < 4; i++) {
                const int8_t* base = sAb + (rbase + i * 16 + g) * SSTRIDE + kk * 32 + j * 4;
                a[i][0] = *(const uint32_t*)(base);
                a[i][1] = *(const uint32_t*)(base + 8 * SSTRIDE);
                a[i][2] = *(const uint32_t*)(base + 16);
                a[i][3] = *(const uint32_t*)(base + 8 * SSTRIDE + 16);
            }
            uint32_t bb[4][2];
#pragma unroll
            for (int nf = 0; nf < 4; nf++) {
                const int8_t* base = sBb + (cbase + nf * 8 + g) * SSTRIDE + kk * 32 + j * 4;
                bb[nf][0] = *(const uint32_t*)(base);
                bb[nf][1] = *(const uint32_t*)(base + 16);
            }
#pragma unroll
            for (int i = 0; i < 4; i++)
#pragma unroll
                for (int nf = 0; nf < 4; nf++)
                    mma_s8(acc[i][nf], a[i], bb[nf]);
        }
        __syncthreads();
    }

#pragma unroll
    for (int i = 0; i < 4; i++) {
        int r0 = m0 + rbase + i * 16 + g;
        float rd0 = g_rdeq[r0];
        float rd1 = g_rdeq[r0 + 8];
#pragma unroll
        for (int nf = 0; nf < 4; nf++) {
            int cc = n0 + cbase + nf * 8 + j * 2;
            float b0v = g_bq[cc], b1v = g_bq[cc + 1];
            float2 v0, v1;
            v0.x = ((float)acc[i][nf][0] + b0v) * rd0;
            v0.y = ((float)acc[i][nf][1] + b1v) * rd0;
            v1.x = ((float)acc[i][nf][2] + b0v) * rd1;
            v1.y = ((float)acc[i][nf][3] + b1v) * rd1;
            *(float2*)&out[(size_t)r0 * O_DIM + cc]        = v0;
            *(float2*)&out[(size_t)(r0 + 8) * O_DIM + cc]  = v1;
        }
    }
}

// =================== stage 4B: persistent tcgen05 bf16 GEMM, decoupled producer ===================
// (= R15 best: 128 persistent CTAs x 4 tiles (256x256), 288 threads; warp 8 =
// continuous 64-chunk bulk-copy producer; tid0 issues MMAs; 8-warp pipelined epilogue)
#define TILE_M 256
#define TILE_N 256
#define SLOT_BYTES 65536        // A 32KB + B 32KB
#define NSLOT 3
#define NPCTA 128
#define NTPC 4                  // tiles per CTA
#define SM_TMEM      0
#define SM_MB_FULL   8          // 3 x 8B
#define SM_MB_EMPTY  32         // 3 x 8B
#define SM_MB_DONE   56
#define SM_MB_EPIFREE 64
#define SM_BIAS      1024       // 256 floats
#define SM_TP        2048       // 8 warps x 32x33 floats = 33792B
#define SM_TILES     35840      // 1024-aligned, after TP
#define SMEM_TOTAL_GEMM (SM_TILES + NSLOT * SLOT_BYTES)   // 232448

#if defined(__CUDA_ARCH__) && (defined(__CUDA_ARCH_SPECIFIC__) || defined(__CUDA_ARCH_FAMILY_SPECIFIC__))
#define HAS_TCGEN05 1
#else
#define HAS_TCGEN05 0
#endif

#if HAS_TCGEN05
// SW128 K-major smem descriptor (LBO=1, SBO=64, version=1, layout=SW128)
static __device__ __forceinline__ uint64_t make_desc(uint32_t addr) {
    const uint64_t base = (2ULL << 61) | (1ULL << 46) | (64ULL << 32) | (1ULL << 16);
    return base | ((uint64_t)(addr >> 4) & 0x3FFF);
}

// idesc kind::f16: dtype=F32(1)<<4, atype=BF16(1)<<7, btype=BF16(1)<<10, N/8<<17, M/16<<24
#define IDESC_BF16 ((1u << 4) | (1u << 7) | (1u << 10) | ((TILE_N / 8) << 17) | ((128 / 16) << 24))

__device__ __forceinline__ void mma_bf16_ss(uint32_t d_tmem, uint64_t a_desc, uint64_t b_desc,
                                            uint32_t idesc, uint32_t enable) {
    asm volatile(
        "{\n\t.reg .pred p;\n\t"
        "setp.ne.u32 p, %5, 0;\n\t"
        "tcgen05.mma.cta_group::1.kind::f16 [%0], %1, %2, %3, {%4, %4, %4, %4}, p;\n\t}"
        :: "r"(d_tmem), "l"(a_desc), "l"(b_desc), "r"(idesc), "r"(0u), "r"(enable)
        : "memory");
}

__device__ __forceinline__ void bulk_cp(uint32_t dst, const void* src, uint32_t bytes,
                                        uint32_t mbar) {
    asm volatile(
        "cp.async.bulk.shared::cluster.global.mbarrier::complete_tx::bytes [%0], [%1], %2, [%3];"
        :: "r"(dst), "l"(src), "r"(bytes), "r"(mbar) : "memory");
}

#define MBAR_INIT(addr, cnt) \
    asm volatile("mbarrier.init.shared.b64 [%0], %1;" :: "r"(addr), "r"(cnt) : "memory")

#define MBAR_EXPECT_TX(addr, tx) \
    asm volatile("mbarrier.arrive.expect_tx.shared.b64 _, [%0], %1;" :: "r"(addr), "r"(tx) : "memory")

#define MBAR_ARRIVE(addr) \
    asm volatile("mbarrier.arrive.shared.b64 _, [%0];" :: "r"(addr) : "memory")

#define MBAR_WAIT(addr, ph) do {                                              \
    asm volatile(                                                             \
        "{\n\t.reg .pred P;\n\t"                                              \
        "W%=:\n\t"                                                            \
        "mbarrier.try_wait.parity.acquire.cta.shared::cta.b64 P, [%0], %1, 0x989680;\n\t" \
        "@P bra.uni D%=;\n\t"                                                 \
        "bra.uni W%=;\n\t"                                                    \
        "D%=:\n\t}"                                                           \
        :: "r"(addr), "r"(ph) : "memory");                                    \
} while (0)

#define TC_COMMIT(addr) \
    asm volatile("tcgen05.commit.cta_group::1.mbarrier::arrive::one.shared::cluster.b64 [%0];" \
                 :: "r"(addr) : "memory")

#define TCWAIT_LD() asm volatile("tcgen05.wait::ld.sync.aligned;" ::: "memory")

#define LDTM_X32(r, addr) \
    asm volatile( \
        "tcgen05.ld.sync.aligned.32x32b.x32.b32 " \
        "{%0,%1,%2,%3,%4,%5,%6,%7,%8,%9,%10,%11,%12,%13,%14,%15," \
        "%16,%17,%18,%19,%20,%21,%22,%23,%24,%25,%26,%27,%28,%29,%30,%31}, [%32];" \
        : "=r"((r)[0]),  "=r"((r)[1]),  "=r"((r)[2]),  "=r"((r)[3]), \
          "=r"((r)[4]),  "=r"((r)[5]),  "=r"((r)[6]),  "=r"((r)[7]), \
          "=r"((r)[8]),  "=r"((r)[9]),  "=r"((r)[10]), "=r"((r)[11]), \
          "=r"((r)[12]), "=r"((r)[13]), "=r"((r)[14]), "=r"((r)[15]), \
          "=r"((r)[16]), "=r"((r)[17]), "=r"((r)[18]), "=r"((r)[19]), \
          "=r"((r)[20]), "=r"((r)[21]), "=r"((r)[22]), "=r"((r)[23]), \
          "=r"((r)[24]), "=r"((r)[25]), "=r"((r)[26]), "=r"((r)[27]), \
          "=r"((r)[28]), "=r"((r)[29]), "=r"((r)[30]), "=r"((r)[31]) \
        : "r"(addr))

// process one 32-col chunk: bias+dequant -> warp transpose -> coalesced stores
#define EPI_PROC(d, cb) do {                                                         \
    _Pragma("unroll")                                                                \
    for (int k_ = 0; k_ < 32; k_++)                                                  \
        tp[lane * 33 + k_] = (__uint_as_float((d)[k_]) + sbias[(cb) * 32 + k_]) * rd; \
    __syncwarp();                                                                    \
    _Pragma("unroll")                                                                \
    for (int r_ = 0; r_ < 32; r_++)                                                  \
        out[(size_t)(rowbase + r_) * O_DIM + n0 + (cb) * 32 + lane] = tp[r_ * 33 + lane]; \
    __syncwarp();                                                                    \
} while (0)
#endif  // HAS_TCGEN05

__global__ void __launch_bounds__(288, 1)
gemm_tc_kernel(float* __restrict__ out, int M) {
#if HAS_TCGEN05
    extern __shared__ __align__(1024) char smem[];
    uint32_t sbase = smem_u32(smem);
    int tid = threadIdx.x;
    int wid = tid >> 5, lane = tid & 31;

    const int TOTC = NTPC * NCHUNK;   // 64 chunks per CTA

    if (wid == 0) {
        asm volatile("tcgen05.alloc.cta_group::1.sync.aligned.shared::cta.b32 [%0], %1;"
                     :: "r"(sbase + SM_TMEM), "r"(512) : "memory");
        asm volatile("tcgen05.relinquish_alloc_permit.cta_group::1.sync.aligned;");
    }
    if (tid == 0) {
#pragma unroll
        for (int i = 0; i < NSLOT; i++) {
            MBAR_INIT(sbase + SM_MB_FULL + i * 8, 1);
            MBAR_INIT(sbase + SM_MB_EMPTY + i * 8, 1);
        }
        MBAR_INIT(sbase + SM_MB_DONE, 1);
        MBAR_INIT(sbase + SM_MB_EPIFREE, 256);
    }
    // bias staged ONCE: n0 is the same for all NTPC tiles of this CTA
    int n0 = ((int)blockIdx.x & 3) * TILE_N;
    if (tid < 256) ((float*)(smem + SM_BIAS))[tid] = g_bq[n0 + tid];
    __syncthreads();

    uint32_t tmem_base;
    asm volatile("ld.shared.b32 %0, [%1];" : "=r"(tmem_base) : "r"(sbase + SM_TMEM));

    const char* abase = (const char*)g_xb;
    const char* bbase = (const char*)g_wb;

    if (wid == 8) {
        // ============ copy producer: continuous 64-chunk stream ============
        if (lane == 0) {
            unsigned eph = 0;
            for (int g = 0; g < TOTC; g++) {
                int slot = g % NSLOT;
                if (g >= NSLOT) {
                    uint32_t eb = sbase + SM_MB_EMPTY + slot * 8;
                    MBAR_WAIT(eb, (eph >> slot) & 1);
                    eph ^= (1u << slot);
                }
                int gt = blockIdx.x + (g >> 4) * NPCTA;
                int m0 = (gt >> 2) * TILE_M;
                int ck = g & 15;
                uint32_t fb = sbase + SM_MB_FULL + slot * 8;
                uint32_t sl = sbase + SM_TILES + slot * SLOT_BYTES;
                MBAR_EXPECT_TX(fb, (uint32_t)SLOT_BYTES);
                bulk_cp(sl,         abase + ((size_t)ck * M + m0) * 128,     32768, fb);
                bulk_cp(sl + 32768, bbase + ((size_t)ck * O_DIM + n0) * 128, 32768, fb);
            }
        }
    } else {
        // ============ MMA issuer (tid0) + epilogue warps 0-7 ============
        const float* sbias = (const float*)(smem + SM_BIAS);
        float* tp = (float*)(smem + SM_TP) + wid * (32 * 33);
        unsigned fph = 0;
        int dph = 0, efph = 0;
        int eh = wid >> 2;          // M-half
        int esp = wid & 3;          // 32-row subpartition

        for (int tl = 0; tl < NTPC; tl++) {
            int gt = blockIdx.x + tl * NPCTA;
            int m0 = (gt >> 2) * TILE_M;

            if (tid == 0) {
                if (tl > 0) {
                    MBAR_WAIT(sbase + SM_MB_EPIFREE, efph);
                    efph ^= 1;
                    asm volatile("tcgen05.fence::after_thread_sync;" ::: "memory");
                }
                for (int s = 0; s < NCHUNK; s++) {
                    int g = tl * NCHUNK + s;
                    int slot = g % NSLOT;
                    uint32_t fb = sbase + SM_MB_FULL + slot * 8;
                    uint32_t sl = sbase + SM_TILES + slot * SLOT_BYTES;

                    MBAR_WAIT(fb, (fph >> slot) & 1);
                    fph ^= (1u << slot);

                    uint64_t a_base = make_desc(sl);
                    uint64_t b_base = make_desc(sl + 32768);
#pragma unroll
                    for (int h = 0; h < 2; h++) {
#pragma unroll
                        for (int k = 0; k < 4; k++) {
                            mma_bf16_ss(tmem_base + h * TILE_N,
                                        a_base + h * 1024 + k * 2,
                                        b_base + k * 2,
                                        IDESC_BF16,
                                        (s > 0 || k > 0) ? 1u : 0u);
                        }
                    }
                    if (g + NSLOT < TOTC) {
                        TC_COMMIT(sbase + SM_MB_EMPTY + slot * 8);
                    }
                }
                TC_COMMIT(sbase + SM_MB_DONE);
            }

            // all epilogue threads wait for this tile's MMAs to retire
            MBAR_WAIT(sbase + SM_MB_DONE, dph);
            dph ^= 1;
            asm volatile("tcgen05.fence::after_thread_sync;" ::: "memory");

            // epilogue: software-pipelined LDTM pairs; 8 warps
            {
                int rowbase = m0 + eh * 128 + esp * 32;
                float rd = g_rdeq[rowbase + lane];
                uint32_t tb = tmem_base + eh * TILE_N;
                uint32_t da[32], db[32], dc[32], dd[32];

                LDTM_X32(da, tb);       LDTM_X32(db, tb + 32);
                TCWAIT_LD();
                LDTM_X32(dc, tb + 64);  LDTM_X32(dd, tb + 96);
                EPI_PROC(da, 0);        EPI_PROC(db, 1);
                TCWAIT_LD();
                LDTM_X32(da, tb + 128); LDTM_X32(db, tb + 160);
                EPI_PROC(dc, 2);        EPI_PROC(dd, 3);
                TCWAIT_LD();
                LDTM_X32(dc, tb + 192); LDTM_X32(dd, tb + 224);
                EPI_PROC(da, 4);        EPI_PROC(db, 5);
                TCWAIT_LD();
                EPI_PROC(dc, 6);        EPI_PROC(dd, 7);
            }
            asm volatile("tcgen05.fence::before_thread_sync;" ::: "memory");
            MBAR_ARRIVE(sbase + SM_MB_EPIFREE);
        }
    }

    __syncthreads();
    if (wid == 0) {
        asm volatile("tcgen05.dealloc.cta_group::1.sync.aligned.b32 %0, %1;"
                     :: "r"(tmem_base), "r"(512));
    }
#else
    (void)out; (void)M;   // base-arch pass: stub (never launched)
#endif
}

// ---------------- launch ----------------
extern "C" void kernel_launch(void* const* d_in, const int* in_sizes, int n_in,
                              void* d_out, int out_size) {
    const float* x = (const float*)d_in[0];
    const float* w = (const float*)d_in[1];
    const float* b = (const float*)d_in[2];
    float* out = (float*)d_out;

    int M = in_sizes[0] / D_DIM;   // 32768

    cudaFuncAttributes fa;
    bool has_tc = false;
    if (cudaFuncGetAttributes(&fa, (const void*)gemm_tc_kernel) == cudaSuccess)
        has_tc = (fa.numRegs >= 32);

    stats_kernel<<<1025, 256>>>(w, b);

    if (has_tc) {
        quant_fused_tc_kernel<<<M / 8 + 1025, 256>>>(x, w, b, M);
        cudaFuncSetAttribute(gemm_tc_kernel,
                             cudaFuncAttributeMaxDynamicSharedMemorySize, SMEM_TOTAL_GEMM);
        gemm_tc_kernel<<<NPCTA, 288, SMEM_TOTAL_GEMM>>>(out, M);
    } else {
        quant_wb_kernel<<<1025, 256>>>(w, b);
        quant_x_kernel<<<M / 8, 256>>>(x);
        dim3 grid(O_DIM / BN, M / BM);
        gemm_kernel<<<grid, 256>>>(out, M);
    }
}